// round 17
// baseline (speedup 1.0000x reference)
#include <cuda_runtime.h>
#include <cuda_fp16.h>

#define N_NODES 100000
#define N_EDGES 1600000
#define D 48

#define T 256
#define N_TILES (N_NODES / 16)                           // 6250 (exact)
#define N_PAIRS ((N_TILES + 1) / 2)                      // 3125 tile-pairs
#define MMA_BLOCKS 160                                   // 1280 persistent warps
#define MMA_WARPS (MMA_BLOCKS * (T / 32))

// Device scratch (no allocations allowed):
__device__ __half g_agg0[N_NODES * D];   // fp16 accumulator, even edges (9.6 MB)
__device__ __half g_agg1[N_NODES * D];   // fp16 accumulator, odd edges  (9.6 MB)

// ---------------------------------------------------------------------------
// Kernel 1: COO scatter straight from fp32 x: agg[dst] += a_e * x[src].
// 6 lanes per edge; lane c loads 8 fp32 (32 B, L2-resident), scales, rounds
// to fp16 once, and issues ONE red.v4.f16x2 (16 B) -> contiguous 96 B/edge.
// Edge parity selects the accumulator buffer (shorter fp16 chains).
// ---------------------------------------------------------------------------
__global__ void scatter_kernel(const float* __restrict__ x,
                               const int* __restrict__ src,
                               const int* __restrict__ dst,
                               const float* __restrict__ vals) {
    int tid = blockIdx.x * blockDim.x + threadIdx.x;
    if (tid >= N_EDGES * 6) return;
    int e = tid / 6;
    int c = tid - e * 6;

    int s = __ldg(src + e);
    int d = __ldg(dst + e);
    float a = __ldg(vals + e);

    const float4* xp = (const float4*)(x + (size_t)s * D + c * 8);
    float4 v0 = __ldg(xp);
    float4 v1 = __ldg(xp + 1);

    __half2 h[4];
    h[0] = __floats2half2_rn(a * v0.x, a * v0.y);
    h[1] = __floats2half2_rn(a * v0.z, a * v0.w);
    h[2] = __floats2half2_rn(a * v1.x, a * v1.y);
    h[3] = __floats2half2_rn(a * v1.z, a * v1.w);

    __half* base = (e & 1) ? g_agg1 : g_agg0;
    __half* p = base + (size_t)d * D + c * 8;
    asm volatile("red.global.add.noftz.v4.f16x2 [%0], {%1, %2, %3, %4};"
                 :: "l"(p),
                    "r"(*(const unsigned*)&h[0]), "r"(*(const unsigned*)&h[1]),
                    "r"(*(const unsigned*)&h[2]), "r"(*(const unsigned*)&h[3])
                 : "memory");
}

// ---------------------------------------------------------------------------
// Kernel 2: out = relu((agg0 + agg1) @ w + b) via HMMA m16n8k16.
// Persistent warps, direct-LDG A-path (R12-proven), TWO tiles per iteration:
// both tiles' A-fragment loads are issued before either tile's HMMAs,
// doubling loads-in-flight per warp. B-fragments shared across all tiles.
// ---------------------------------------------------------------------------
__global__ void __launch_bounds__(256, 2)
mma_finalize_kernel(const float* __restrict__ w,
                    const float* __restrict__ b,
                    float* __restrict__ out) {
    __shared__ float ws[D * D];
    __shared__ float bs[D];
    for (int i = threadIdx.x; i < D * D; i += blockDim.x) ws[i] = w[i];
    if (threadIdx.x < D) bs[threadIdx.x] = b[threadIdx.x];
    __syncthreads();

    int gwarp = ((blockIdx.x * blockDim.x + threadIdx.x) >> 5);
    int lane = threadIdx.x & 31;
    int gid = lane >> 2;        // group id 0..7
    int tig = lane & 3;         // thread in group 0..3

    // --- B fragments: w (fp32, smem) -> fp16 regs. Built ONCE per warp.
    unsigned bf[3][6][2];
#pragma unroll
    for (int kt = 0; kt < 3; kt++) {
#pragma unroll
        for (int nt = 0; nt < 6; nt++) {
            int n  = nt * 8 + gid;
            int k0 = kt * 16 + tig * 2;
            __half2 h0 = __floats2half2_rn(ws[k0 * D + n], ws[(k0 + 1) * D + n]);
            __half2 h1 = __floats2half2_rn(ws[(k0 + 8) * D + n], ws[(k0 + 9) * D + n]);
            bf[kt][nt][0] = *(const unsigned*)&h0;
            bf[kt][nt][1] = *(const unsigned*)&h1;
        }
    }
    float2 bias[6];
#pragma unroll
    for (int nt = 0; nt < 6; nt++)
        bias[nt] = *(const float2*)(bs + nt * 8 + tig * 2);

    // --- tile-pair loop (persistent) ---
    for (int pair = gwarp; pair < N_PAIRS; pair += MMA_WARPS) {
        int tileA = pair * 2;
        int tileB = tileA + 1;                 // N_TILES even -> always valid
        int nbA = tileA * 16;
        int nbB = tileB * 16;
        const __half* a0A = g_agg0 + (size_t)nbA * D;
        const __half* a1A = g_agg1 + (size_t)nbA * D;
        const __half* a0B = g_agg0 + (size_t)nbB * D;
        const __half* a1B = g_agg1 + (size_t)nbB * D;

        float accA[6][4], accB[6][4];
#pragma unroll
        for (int nt = 0; nt < 6; nt++)
#pragma unroll
            for (int t = 0; t < 4; t++) { accA[nt][t] = 0.f; accB[nt][t] = 0.f; }

#pragma unroll
        for (int kt = 0; kt < 3; kt++) {
            int c0 = kt * 16 + tig * 2;
            unsigned aA[4], aB[4];
            // issue ALL eight tile loads (16 LDG.32 pairs) before any math
#pragma unroll
            for (int t = 0; t < 4; t++) {
                int r = gid + ((t & 1) ? 8 : 0);
                int c = c0 + ((t & 2) ? 8 : 0);
                __half2 vA0 = *(const __half2*)(a0A + r * D + c);
                __half2 vA1 = *(const __half2*)(a1A + r * D + c);
                __half2 vB0 = *(const __half2*)(a0B + r * D + c);
                __half2 vB1 = *(const __half2*)(a1B + r * D + c);
                __half2 sA = __hadd2(vA0, vA1);
                __half2 sB = __hadd2(vB0, vB1);
                aA[t] = *(const unsigned*)&sA;
                aB[t] = *(const unsigned*)&sB;
            }
#pragma unroll
            for (int nt = 0; nt < 6; nt++) {
                asm volatile(
                    "mma.sync.aligned.m16n8k16.row.col.f32.f16.f16.f32 "
                    "{%0,%1,%2,%3}, {%4,%5,%6,%7}, {%8,%9}, {%0,%1,%2,%3};"
                    : "+f"(accA[nt][0]), "+f"(accA[nt][1]),
                      "+f"(accA[nt][2]), "+f"(accA[nt][3])
                    : "r"(aA[0]), "r"(aA[1]), "r"(aA[2]), "r"(aA[3]),
                      "r"(bf[kt][nt][0]), "r"(bf[kt][nt][1]));
                asm volatile(
                    "mma.sync.aligned.m16n8k16.row.col.f32.f16.f16.f32 "
                    "{%0,%1,%2,%3}, {%4,%5,%6,%7}, {%8,%9}, {%0,%1,%2,%3};"
                    : "+f"(accB[nt][0]), "+f"(accB[nt][1]),
                      "+f"(accB[nt][2]), "+f"(accB[nt][3])
                    : "r"(aB[0]), "r"(aB[1]), "r"(aB[2]), "r"(aB[3]),
                      "r"(bf[kt][nt][0]), "r"(bf[kt][nt][1]));
            }
        }

#pragma unroll
        for (int nt = 0; nt < 6; nt++) {
            int col = nt * 8 + tig * 2;
            float2 v0, v1;
            v0.x = fmaxf(accA[nt][0] + bias[nt].x, 0.f);
            v0.y = fmaxf(accA[nt][1] + bias[nt].y, 0.f);
            v1.x = fmaxf(accA[nt][2] + bias[nt].x, 0.f);
            v1.y = fmaxf(accA[nt][3] + bias[nt].y, 0.f);
            *(float2*)(out + (size_t)(nbA + gid) * D + col)     = v0;
            *(float2*)(out + (size_t)(nbA + gid + 8) * D + col) = v1;
            v0.x = fmaxf(accB[nt][0] + bias[nt].x, 0.f);
            v0.y = fmaxf(accB[nt][1] + bias[nt].y, 0.f);
            v1.x = fmaxf(accB[nt][2] + bias[nt].x, 0.f);
            v1.y = fmaxf(accB[nt][3] + bias[nt].y, 0.f);
            *(float2*)(out + (size_t)(nbB + gid) * D + col)     = v0;
            *(float2*)(out + (size_t)(nbB + gid + 8) * D + col) = v1;
        }
    }
}

// ---------------------------------------------------------------------------
extern "C" void kernel_launch(void* const* d_in, const int* in_sizes, int n_in,
                              void* d_out, int out_size) {
    const float* x        = (const float*)d_in[0];
    const float* w        = (const float*)d_in[1];
    const float* b        = (const float*)d_in[2];
    const int*   edge_src = (const int*)d_in[3];
    const int*   edge_dst = (const int*)d_in[4];
    const float* adj_vals = (const float*)d_in[5];
    float* out = (float*)d_out;

    // 1) zero both agg buffers via graph-capturable memset nodes
    void* a0p = nullptr;
    void* a1p = nullptr;
    cudaGetSymbolAddress(&a0p, g_agg0);
    cudaGetSymbolAddress(&a1p, g_agg1);
    cudaMemsetAsync(a0p, 0, (size_t)N_NODES * D * sizeof(__half), 0);
    cudaMemsetAsync(a1p, 0, (size_t)N_NODES * D * sizeof(__half), 0);

    // 2) scatter straight from fp32 x: agg[dst] += a_e * x[src]
    {
        int total = N_EDGES * 6;
        scatter_kernel<<<(total + T - 1) / T, T>>>(x, edge_src, edge_dst, adj_vals);
    }
    // 3) out = relu((agg0 + agg1) @ w + b): direct-LDG HMMA, 2 tiles in flight
    mma_finalize_kernel<<<MMA_BLOCKS, T>>>(w, b, out);
}